// round 6
// baseline (speedup 1.0000x reference)
#include <cuda_runtime.h>
#include <stdint.h>

#define SEQ   8192
#define DKE   64
#define QT    128          // query rows per CTA
#define KT    64           // keys per tile
#define CHUNK 1024         // keys per split-K chunk
#define NQT   (SEQ/QT)     // 64
#define MAXC  (SEQ/CHUNK)  // 8
#define CPT   (CHUNK/QT)   // 8
#define WROWS 16           // q rows per warp
#define NTILE (SEQ/KT)     // 128 key tiles
#define TW    4096         // uint32 words per K (or V) tile block
#define STG   3            // cp.async pipeline stages
#define SWORDS (2*TW)      // words per stage (K+V)

// scratch (__device__ globals; no allocation)
__device__ float    g_pout[MAXC][SEQ][DKE];
__device__ float    g_pm[MAXC][SEQ];      // row max (log2 domain)
__device__ float    g_pl[MAXC][SEQ];
__device__ uint32_t g_kf[NTILE][TW];      // K tiles, tf32, fragment-major
__device__ uint32_t g_vf[NTILE][TW];      // V tiles, tf32, fragment-major

__device__ __forceinline__ uint32_t f2tf32(float x) {
    uint32_t r;
    asm("cvt.rna.tf32.f32 %0, %1;" : "=r"(r) : "f"(x));
    return r;
}
__device__ __forceinline__ float ex2f(float x) {
    float r;
    asm("ex2.approx.ftz.f32 %0, %1;" : "=f"(r) : "f"(x));
    return r;
}
__device__ __forceinline__ void mma_tf32(float c[4], const uint32_t a[4],
                                         uint32_t b0, uint32_t b1) {
    asm("mma.sync.aligned.m16n8k8.row.col.f32.tf32.tf32.f32 "
        "{%0,%1,%2,%3}, {%4,%5,%6,%7}, {%8,%9}, {%0,%1,%2,%3};"
        : "+f"(c[0]), "+f"(c[1]), "+f"(c[2]), "+f"(c[3])
        : "r"(a[0]), "r"(a[1]), "r"(a[2]), "r"(a[3]), "r"(b0), "r"(b1));
}
__device__ __forceinline__ void cp16(uint32_t saddr, const void* g) {
    asm volatile("cp.async.cg.shared.global [%0], [%1], 16;"
                 :: "r"(saddr), "l"(g));
}
#define CP_COMMIT() asm volatile("cp.async.commit_group;")
#define CP_WAIT1()  asm volatile("cp.async.wait_group 1;")
#define CP_WAIT0()  asm volatile("cp.async.wait_group 0;")

// Q prescale: 1/64 (problem scale) * log2(e)
#define QSCALE (0.015625f * 1.44269504088896340736f)

// ---- prep: K/V -> tf32, fragment-major swizzled tile blocks ----
__global__ __launch_bounds__(256)
void prep_kv(const float* __restrict__ k, const float* __restrict__ v) {
    const int tile = blockIdx.x;
    const int tid  = threadIdx.x;
    const float4* kg = (const float4*)(k + (size_t)tile * KT * DKE);
    const float4* vg = (const float4*)(v + (size_t)tile * KT * DKE);
    uint32_t* kd = g_kf[tile];
    uint32_t* vd = g_vf[tile];
    #pragma unroll
    for (int i = 0; i < 4; i++) {
        int idx = tid + i * 256;      // float4 index 0..1023
        int r   = idx >> 4;           // key row in tile
        int c0  = (idx & 15) << 2;    // dim base
        // K: nb=r>>3, g=r&7; ka=c>>3, t=c&3, hi=(c>>2)&1; slot=g*4+(t^kap)
        {
            float4 x = kg[idx];
            int nb = r >> 3, gg = r & 7;
            int ka = c0 >> 3, kap = ka >> 1;
            int hi = (c0 >> 2) & 1;
            int e  = (ka & 1) * 2 + hi;
            uint32_t* base = kd + (nb * 4 + kap) * 128;
            base[((gg * 4 + (0 ^ kap)) << 2) + e] = f2tf32(x.x);
            base[((gg * 4 + (1 ^ kap)) << 2) + e] = f2tf32(x.y);
            base[((gg * 4 + (2 ^ kap)) << 2) + e] = f2tf32(x.z);
            base[((gg * 4 + (3 ^ kap)) << 2) + e] = f2tf32(x.w);
        }
        // V: ksq=r>>3, tt=r&3, hi=(r>>2)&1; nb=c>>3, gv=c&7
        {
            float4 y = vg[idx];
            int ksq = r >> 3, tt = r & 3;
            int hi  = (r >> 2) & 1;
            int nb  = c0 >> 3, nbp = nb >> 1;
            int e   = (nb & 1) * 2 + hi;
            int g0  = c0 & 7;
            uint32_t* base = vd + (ksq * 4 + nbp) * 128;
            #pragma unroll
            for (int j = 0; j < 4; j++) {
                int z  = (g0 + j) * 4 + tt;
                int xl = (z ^ nbp) ^ ((z & 16) >> 2);
                float val = (j == 0) ? y.x : (j == 1) ? y.y : (j == 2) ? y.z : y.w;
                base[(xl << 2) + e] = f2tf32(val);
            }
        }
    }
}

__global__ __launch_bounds__(256, 2)
void attn_phase1(const float* __restrict__ q) {
    const int m = blockIdx.y;
    const int c = blockIdx.x;
    if (c > m / CPT) return;

    extern __shared__ uint32_t smem[];   // STG stages x (K 4096 | V 4096)

    const int tid  = threadIdx.x;
    const int w    = tid >> 5;
    const int lane = tid & 31;
    const int g    = lane >> 2;
    const int t    = lane & 3;
    const int row_base = m * QT + w * WROWS;
    const int row0 = row_base + g;
    const int row1 = row0 + 8;

    const uint32_t sbase = (uint32_t)__cvta_generic_to_shared(smem);

    const int kstart  = c * CHUNK;
    const int kend    = min(kstart + CHUNK, (m + 1) * QT);
    const int ntiles  = (kend - kstart) / KT;
    const int tile0   = kstart / KT;

    // ---- prologue: prefetch tiles 0,1 ----
    #pragma unroll
    for (int p = 0; p < 2; p++) {
        if (p < ntiles) {
            uint32_t sa = sbase + (p * SWORDS) * 4;
            const uint4* ksrc = (const uint4*)g_kf[tile0 + p];
            const uint4* vsrc = (const uint4*)g_vf[tile0 + p];
            #pragma unroll
            for (int j = 0; j < 4; j++) {
                int o4 = tid + j * 256;           // uint4 index 0..1023
                cp16(sa + o4 * 16,            ksrc + o4);
                cp16(sa + (TW + o4 * 4) * 4,  vsrc + o4);
            }
        }
        CP_COMMIT();
    }

    // ---- Q fragments (prescaled, tf32) ----
    uint32_t qA[8][4];
    #pragma unroll
    for (int ka = 0; ka < 8; ka++) {
        qA[ka][0] = f2tf32(q[(size_t)row0 * DKE + ka * 8 + t]     * QSCALE);
        qA[ka][1] = f2tf32(q[(size_t)row1 * DKE + ka * 8 + t]     * QSCALE);
        qA[ka][2] = f2tf32(q[(size_t)row0 * DKE + ka * 8 + t + 4] * QSCALE);
        qA[ka][3] = f2tf32(q[(size_t)row1 * DKE + ka * 8 + t + 4] * QSCALE);
    }

    float o[8][4];
    #pragma unroll
    for (int nb = 0; nb < 8; nb++)
        o[nb][0] = o[nb][1] = o[nb][2] = o[nb][3] = 0.f;
    float m0 = -1e30f, m1 = -1e30f, l0 = 0.f, l1 = 0.f;

    const int src1  = (lane & ~3) | (t >> 1);
    const int src2  = src1 + 2;
    const bool todd = (t & 1);
    int xlv[4];
    #pragma unroll
    for (int nbp = 0; nbp < 4; nbp++)
        xlv[nbp] = (lane ^ nbp) ^ ((lane & 16) >> 2);

    for (int i = 0; i < ntiles; i++) {
        CP_WAIT1();                    // tile i resident
        __syncthreads();               // all warps done with stage (i+2)%STG (tile i-1)

        // prefetch tile i+2 into stage (i+2)%STG
        if (i + 2 < ntiles) {
            int st = (i + 2) % STG;
            uint32_t sa = sbase + (st * SWORDS) * 4;
            const uint4* ksrc = (const uint4*)g_kf[tile0 + i + 2];
            const uint4* vsrc = (const uint4*)g_vf[tile0 + i + 2];
            #pragma unroll
            for (int j = 0; j < 4; j++) {
                int o4 = tid + j * 256;
                cp16(sa + o4 * 16,           ksrc + o4);
                cp16(sa + (TW + o4 * 4) * 4, vsrc + o4);
            }
        }
        CP_COMMIT();

        const int kt = kstart + i * KT;
        if (kt > row_base + WROWS - 1) continue;  // fully masked for this warp

        const uint32_t* ksf = smem + (i % STG) * SWORDS;
        const uint32_t* vsf = ksf + TW;

        // ---- S = Q K^T ----
        float s[8][4];
        #pragma unroll
        for (int nb = 0; nb < 8; nb++)
            s[nb][0] = s[nb][1] = s[nb][2] = s[nb][3] = 0.f;
        #pragma unroll
        for (int nb = 0; nb < 8; nb++) {
            #pragma unroll
            for (int kap = 0; kap < 4; kap++) {
                uint4 b = *(const uint4*)&ksf[((nb * 4 + kap) * 32 + (lane ^ kap)) * 4];
                mma_tf32(s[nb], qA[2 * kap],     b.x, b.y);
                mma_tf32(s[nb], qA[2 * kap + 1], b.z, b.w);
            }
        }

        // ---- causal mask ----
        if (kt + KT - 1 > row_base) {
            #pragma unroll
            for (int nb = 0; nb < 8; nb++) {
                int j0 = kt + nb * 8 + 2 * t;
                int j1 = j0 + 1;
                if (j0 > row0) s[nb][0] = -1e30f;
                if (j1 > row0) s[nb][1] = -1e30f;
                if (j0 > row1) s[nb][2] = -1e30f;
                if (j1 > row1) s[nb][3] = -1e30f;
            }
        }

        // ---- online softmax (log2 domain) ----
        float mx0 = m0, mx1 = m1;
        #pragma unroll
        for (int nb = 0; nb < 8; nb++) {
            mx0 = fmaxf(mx0, fmaxf(s[nb][0], s[nb][1]));
            mx1 = fmaxf(mx1, fmaxf(s[nb][2], s[nb][3]));
        }
        mx0 = fmaxf(mx0, __shfl_xor_sync(0xffffffffu, mx0, 1));
        mx0 = fmaxf(mx0, __shfl_xor_sync(0xffffffffu, mx0, 2));
        mx1 = fmaxf(mx1, __shfl_xor_sync(0xffffffffu, mx1, 1));
        mx1 = fmaxf(mx1, __shfl_xor_sync(0xffffffffu, mx1, 2));

        float sc0 = ex2f(m0 - mx0);
        float sc1 = ex2f(m1 - mx1);
        m0 = mx0; m1 = mx1;
        #pragma unroll
        for (int nb = 0; nb < 8; nb++) {
            o[nb][0] *= sc0; o[nb][1] *= sc0;
            o[nb][2] *= sc1; o[nb][3] *= sc1;
        }

        float ps0 = 0.f, ps1 = 0.f;
        #pragma unroll
        for (int nb = 0; nb < 8; nb++) {
            s[nb][0] = ex2f(s[nb][0] - m0);
            s[nb][1] = ex2f(s[nb][1] - m0);
            s[nb][2] = ex2f(s[nb][2] - m1);
            s[nb][3] = ex2f(s[nb][3] - m1);
            ps0 += s[nb][0] + s[nb][1];
            ps1 += s[nb][2] + s[nb][3];
        }
        ps0 += __shfl_xor_sync(0xffffffffu, ps0, 1);
        ps0 += __shfl_xor_sync(0xffffffffu, ps0, 2);
        ps1 += __shfl_xor_sync(0xffffffffu, ps1, 1);
        ps1 += __shfl_xor_sync(0xffffffffu, ps1, 2);
        l0 = l0 * sc0 + ps0;
        l1 = l1 * sc1 + ps1;

        // ---- O += P V ----
        #pragma unroll
        for (int ksq = 0; ksq < 8; ksq++) {
            float v00 = __shfl_sync(0xffffffffu, s[ksq][0], src1);
            float v01 = __shfl_sync(0xffffffffu, s[ksq][1], src1);
            float v02 = __shfl_sync(0xffffffffu, s[ksq][0], src2);
            float v03 = __shfl_sync(0xffffffffu, s[ksq][1], src2);
            float v10 = __shfl_sync(0xffffffffu, s[ksq][2], src1);
            float v11 = __shfl_sync(0xffffffffu, s[ksq][3], src1);
            float v12 = __shfl_sync(0xffffffffu, s[ksq][2], src2);
            float v13 = __shfl_sync(0xffffffffu, s[ksq][3], src2);
            uint32_t pA[4];
            pA[0] = f2tf32(todd ? v01 : v00);
            pA[1] = f2tf32(todd ? v11 : v10);
            pA[2] = f2tf32(todd ? v03 : v02);
            pA[3] = f2tf32(todd ? v13 : v12);
            #pragma unroll
            for (int nbp = 0; nbp < 4; nbp++) {
                uint4 b = *(const uint4*)&vsf[((ksq * 4 + nbp) * 32 + xlv[nbp]) * 4];
                mma_tf32(o[2 * nbp],     pA, b.x, b.y);
                mma_tf32(o[2 * nbp + 1], pA, b.z, b.w);
            }
        }
    }
    CP_WAIT0();   // drain before exit (stage smem may be reallocated)

    // ---- write split-K partials ----
    #pragma unroll
    for (int nb = 0; nb < 8; nb++) {
        *(float2*)&g_pout[c][row0][nb * 8 + 2 * t] = make_float2(o[nb][0], o[nb][1]);
        *(float2*)&g_pout[c][row1][nb * 8 + 2 * t] = make_float2(o[nb][2], o[nb][3]);
    }
    if (t == 0) {
        g_pm[c][row0] = m0; g_pl[c][row0] = l0;
        g_pm[c][row1] = m1; g_pl[c][row1] = l1;
    }
}

// Combine: one warp per row. Fully unrolled; inactive chunks are zero-filled
// (.bss) so they contribute exactly 0 — branch-free, max MLP.
__global__ __launch_bounds__(256)
void attn_phase2(float* __restrict__ out) {
    const int row  = blockIdx.x * 8 + (threadIdx.x >> 5);
    const int lane = threadIdx.x & 31;

    float pm[MAXC], pl[MAXC];
    #pragma unroll
    for (int c = 0; c < MAXC; c++) { pm[c] = g_pm[c][row]; pl[c] = g_pl[c][row]; }

    float gmax = pm[0];
    #pragma unroll
    for (int c = 1; c < MAXC; c++) gmax = fmaxf(gmax, pm[c]);

    float denom = 0.f, o0 = 0.f, o1 = 0.f;
    #pragma unroll
    for (int c = 0; c < MAXC; c++) {
        float w = ex2f(pm[c] - gmax);
        denom = fmaf(w, pl[c], denom);
        o0 = fmaf(w, g_pout[c][row][lane],      o0);
        o1 = fmaf(w, g_pout[c][row][lane + 32], o1);
    }
    float inv = 1.0f / denom;
    out[(size_t)row * DKE + lane]      = o0 * inv;
    out[(size_t)row * DKE + lane + 32] = o1 * inv;
}

extern "C" void kernel_launch(void* const* d_in, const int* in_sizes, int n_in,
                              void* d_out, int out_size) {
    const float* q = (const float*)d_in[0];
    const float* k = (const float*)d_in[1];
    const float* v = (const float*)d_in[2];
    float* out = (float*)d_out;

    const int dsm = STG * SWORDS * 4;   // 96 KB
    cudaFuncSetAttribute(attn_phase1,
                         cudaFuncAttributeMaxDynamicSharedMemorySize, dsm);

    prep_kv<<<NTILE, 256>>>(k, v);
    dim3 grid1(MAXC, NQT);
    attn_phase1<<<grid1, 256, dsm>>>(q);
    attn_phase2<<<SEQ / 8, 256>>>(out);
}

// round 7
// speedup vs baseline: 1.7344x; 1.7344x over previous
#include <cuda_runtime.h>
#include <stdint.h>

#define SEQ   8192
#define DKE   64
#define QT    128          // query rows per CTA
#define KT    64           // keys per tile
#define CHUNK 1024         // keys per split-K chunk
#define NQT   (SEQ/QT)     // 64
#define MAXC  (SEQ/CHUNK)  // 8
#define CPT   (CHUNK/QT)   // 8
#define WROWS 16           // q rows per warp
#define NTILE (SEQ/KT)     // 128 key tiles
#define TW    4096         // uint32 words per K (or V) tile block

// scratch (__device__ globals; no allocation). Zero-init (.bss) is load-time.
__device__ float    g_pout[MAXC][SEQ][DKE];
__device__ float    g_pm[MAXC][SEQ];      // row max (log2 domain)
__device__ float    g_pl[MAXC][SEQ];
__device__ uint32_t g_kf[NTILE][TW];      // K tiles, tf32, fragment-major
__device__ uint32_t g_vf[NTILE][TW];      // V tiles, tf32, fragment-major

__device__ __forceinline__ uint32_t f2tf32(float x) {
    uint32_t r;
    asm("cvt.rna.tf32.f32 %0, %1;" : "=r"(r) : "f"(x));
    return r;
}
__device__ __forceinline__ float ex2f(float x) {
    float r;
    asm("ex2.approx.ftz.f32 %0, %1;" : "=f"(r) : "f"(x));
    return r;
}
__device__ __forceinline__ void mma_tf32(float c[4], const uint32_t a[4],
                                         uint32_t b0, uint32_t b1) {
    asm("mma.sync.aligned.m16n8k8.row.col.f32.tf32.tf32.f32 "
        "{%0,%1,%2,%3}, {%4,%5,%6,%7}, {%8,%9}, {%0,%1,%2,%3};"
        : "+f"(c[0]), "+f"(c[1]), "+f"(c[2]), "+f"(c[3])
        : "r"(a[0]), "r"(a[1]), "r"(a[2]), "r"(a[3]), "r"(b0), "r"(b1));
}
__device__ __forceinline__ void cp16(uint32_t saddr, const void* g) {
    asm volatile("cp.async.cg.shared.global [%0], [%1], 16;"
                 :: "r"(saddr), "l"(g));
}
#define CP_COMMIT() asm volatile("cp.async.commit_group;")
#define CP_WAIT0()  asm volatile("cp.async.wait_group 0;")

// Q prescale: 1/64 (problem scale) * log2(e)
#define QSCALE (0.015625f * 1.44269504088896340736f)

// ---- prep: K/V -> tf32, fragment-major swizzled tile blocks ----
// grid = NTILE*2: each CTA handles half a tile (layout verified by R5 pass).
__global__ __launch_bounds__(256)
void prep_kv(const float* __restrict__ k, const float* __restrict__ v) {
    const int tile = blockIdx.x >> 1;
    const int half = blockIdx.x & 1;
    const int tid  = threadIdx.x;
    const float4* kg = (const float4*)(k + (size_t)tile * KT * DKE);
    const float4* vg = (const float4*)(v + (size_t)tile * KT * DKE);
    uint32_t* kd = g_kf[tile];
    uint32_t* vd = g_vf[tile];
    #pragma unroll
    for (int i = 0; i < 2; i++) {
        int idx = half * 512 + tid + i * 256;   // float4 index 0..1023
        int r   = idx >> 4;           // key row in tile
        int c0  = (idx & 15) << 2;    // dim base
        // K: nb=r>>3, g=r&7; ka=c>>3, kap=ka>>1, hi=(c>>2)&1
        {
            float4 x = kg[idx];
            int nb = r >> 3, gg = r & 7;
            int ka = c0 >> 3, kap = ka >> 1;
            int hi = (c0 >> 2) & 1;
            int e  = (ka & 1) * 2 + hi;
            uint32_t* base = kd + (nb * 4 + kap) * 128;
            base[((gg * 4 + (0 ^ kap)) << 2) + e] = f2tf32(x.x);
            base[((gg * 4 + (1 ^ kap)) << 2) + e] = f2tf32(x.y);
            base[((gg * 4 + (2 ^ kap)) << 2) + e] = f2tf32(x.z);
            base[((gg * 4 + (3 ^ kap)) << 2) + e] = f2tf32(x.w);
        }
        // V: ksq=r>>3, tt=r&3, hi=(r>>2)&1; nb=c>>3, nbp=nb>>1
        {
            float4 y = vg[idx];
            int ksq = r >> 3, tt = r & 3;
            int hi  = (r >> 2) & 1;
            int nb  = c0 >> 3, nbp = nb >> 1;
            int e   = (nb & 1) * 2 + hi;
            int g0  = c0 & 7;
            uint32_t* base = vd + (ksq * 4 + nbp) * 128;
            #pragma unroll
            for (int j = 0; j < 4; j++) {
                int z  = (g0 + j) * 4 + tt;
                int xl = (z ^ nbp) ^ ((z & 16) >> 2);
                float val = (j == 0) ? y.x : (j == 1) ? y.y : (j == 2) ? y.z : y.w;
                base[(xl << 2) + e] = f2tf32(val);
            }
        }
    }
}

__global__ __launch_bounds__(256, 2)
void attn_phase1(const float* __restrict__ q) {
    const int m = blockIdx.y;
    const int c = blockIdx.x;
    if (c > m / CPT) return;

    __shared__ uint32_t ksf[TW];   // 16 KB, fragment-major tf32
    __shared__ uint32_t vsf[TW];   // 16 KB

    const int tid  = threadIdx.x;
    const int w    = tid >> 5;
    const int lane = tid & 31;
    const int g    = lane >> 2;
    const int t    = lane & 3;
    const int row_base = m * QT + w * WROWS;
    const int row0 = row_base + g;
    const int row1 = row0 + 8;

    const uint32_t ksb = (uint32_t)__cvta_generic_to_shared(ksf);
    const uint32_t vsb = (uint32_t)__cvta_generic_to_shared(vsf);

    // ---- Q fragments (prescaled, tf32) ----
    uint32_t qA[8][4];
    #pragma unroll
    for (int ka = 0; ka < 8; ka++) {
        qA[ka][0] = f2tf32(q[(size_t)row0 * DKE + ka * 8 + t]     * QSCALE);
        qA[ka][1] = f2tf32(q[(size_t)row1 * DKE + ka * 8 + t]     * QSCALE);
        qA[ka][2] = f2tf32(q[(size_t)row0 * DKE + ka * 8 + t + 4] * QSCALE);
        qA[ka][3] = f2tf32(q[(size_t)row1 * DKE + ka * 8 + t + 4] * QSCALE);
    }

    float o[8][4];
    #pragma unroll
    for (int nb = 0; nb < 8; nb++)
        o[nb][0] = o[nb][1] = o[nb][2] = o[nb][3] = 0.f;
    float m0 = -1e30f, m1 = -1e30f, l0 = 0.f, l1 = 0.f;

    const int kstart = c * CHUNK;
    const int kend   = min(kstart + CHUNK, (m + 1) * QT);
    const int src1   = (lane & ~3) | (t >> 1);
    const int src2   = src1 + 2;
    const bool todd  = (t & 1);
    int xlv[4];
    #pragma unroll
    for (int nbp = 0; nbp < 4; nbp++)
        xlv[nbp] = (lane ^ nbp) ^ ((lane & 16) >> 2);

    for (int kt = kstart; kt < kend; kt += KT) {
        const int tile = kt / KT;
        __syncthreads();
        // ---- straight async copy of prepped fragment-major tiles ----
        {
            const uint4* ksrc = (const uint4*)g_kf[tile];
            const uint4* vsrc = (const uint4*)g_vf[tile];
            #pragma unroll
            for (int j = 0; j < 4; j++) {
                int o4 = tid + j * 256;           // uint4 index 0..1023
                cp16(ksb + o4 * 16, ksrc + o4);
                cp16(vsb + o4 * 16, vsrc + o4);
            }
            CP_COMMIT();
            CP_WAIT0();
        }
        __syncthreads();

        if (kt > row_base + WROWS - 1) continue;  // fully masked for this warp

        // ---- S = Q K^T (scaled + log2 domain via Q prescale) ----
        float s[8][4];
        #pragma unroll
        for (int nb = 0; nb < 8; nb++)
            s[nb][0] = s[nb][1] = s[nb][2] = s[nb][3] = 0.f;
        #pragma unroll
        for (int nb = 0; nb < 8; nb++) {
            #pragma unroll
            for (int kap = 0; kap < 4; kap++) {
                uint4 b = *(const uint4*)&ksf[((nb * 4 + kap) * 32 + (lane ^ kap)) * 4];
                mma_tf32(s[nb], qA[2 * kap],     b.x, b.y);
                mma_tf32(s[nb], qA[2 * kap + 1], b.z, b.w);
            }
        }

        // ---- causal mask ----
        if (kt + KT - 1 > row_base) {
            #pragma unroll
            for (int nb = 0; nb < 8; nb++) {
                int j0 = kt + nb * 8 + 2 * t;
                int j1 = j0 + 1;
                if (j0 > row0) s[nb][0] = -1e30f;
                if (j1 > row0) s[nb][1] = -1e30f;
                if (j0 > row1) s[nb][2] = -1e30f;
                if (j1 > row1) s[nb][3] = -1e30f;
            }
        }

        // ---- online softmax (log2 domain) ----
        float mx0 = m0, mx1 = m1;
        #pragma unroll
        for (int nb = 0; nb < 8; nb++) {
            mx0 = fmaxf(mx0, fmaxf(s[nb][0], s[nb][1]));
            mx1 = fmaxf(mx1, fmaxf(s[nb][2], s[nb][3]));
        }
        mx0 = fmaxf(mx0, __shfl_xor_sync(0xffffffffu, mx0, 1));
        mx0 = fmaxf(mx0, __shfl_xor_sync(0xffffffffu, mx0, 2));
        mx1 = fmaxf(mx1, __shfl_xor_sync(0xffffffffu, mx1, 1));
        mx1 = fmaxf(mx1, __shfl_xor_sync(0xffffffffu, mx1, 2));

        float sc0 = ex2f(m0 - mx0);
        float sc1 = ex2f(m1 - mx1);
        m0 = mx0; m1 = mx1;
        #pragma unroll
        for (int nb = 0; nb < 8; nb++) {
            o[nb][0] *= sc0; o[nb][1] *= sc0;
            o[nb][2] *= sc1; o[nb][3] *= sc1;
        }

        float ps0 = 0.f, ps1 = 0.f;
        #pragma unroll
        for (int nb = 0; nb < 8; nb++) {
            s[nb][0] = ex2f(s[nb][0] - m0);
            s[nb][1] = ex2f(s[nb][1] - m0);
            s[nb][2] = ex2f(s[nb][2] - m1);
            s[nb][3] = ex2f(s[nb][3] - m1);
            ps0 += s[nb][0] + s[nb][1];
            ps1 += s[nb][2] + s[nb][3];
        }
        ps0 += __shfl_xor_sync(0xffffffffu, ps0, 1);
        ps0 += __shfl_xor_sync(0xffffffffu, ps0, 2);
        ps1 += __shfl_xor_sync(0xffffffffu, ps1, 1);
        ps1 += __shfl_xor_sync(0xffffffffu, ps1, 2);
        l0 = l0 * sc0 + ps0;
        l1 = l1 * sc1 + ps1;

        // ---- O += P V ----
        #pragma unroll
        for (int ksq = 0; ksq < 8; ksq++) {
            float v00 = __shfl_sync(0xffffffffu, s[ksq][0], src1);
            float v01 = __shfl_sync(0xffffffffu, s[ksq][1], src1);
            float v02 = __shfl_sync(0xffffffffu, s[ksq][0], src2);
            float v03 = __shfl_sync(0xffffffffu, s[ksq][1], src2);
            float v10 = __shfl_sync(0xffffffffu, s[ksq][2], src1);
            float v11 = __shfl_sync(0xffffffffu, s[ksq][3], src1);
            float v12 = __shfl_sync(0xffffffffu, s[ksq][2], src2);
            float v13 = __shfl_sync(0xffffffffu, s[ksq][3], src2);
            uint32_t pA[4];
            pA[0] = f2tf32(todd ? v01 : v00);
            pA[1] = f2tf32(todd ? v11 : v10);
            pA[2] = f2tf32(todd ? v03 : v02);
            pA[3] = f2tf32(todd ? v13 : v12);
            #pragma unroll
            for (int nbp = 0; nbp < 4; nbp++) {
                uint4 b = *(const uint4*)&vsf[((ksq * 4 + nbp) * 32 + xlv[nbp]) * 4];
                mma_tf32(o[2 * nbp],     pA, b.x, b.y);
                mma_tf32(o[2 * nbp + 1], pA, b.z, b.w);
            }
        }
    }

    // ---- write split-K partials ----
    #pragma unroll
    for (int nb = 0; nb < 8; nb++) {
        *(float2*)&g_pout[c][row0][nb * 8 + 2 * t] = make_float2(o[nb][0], o[nb][1]);
        *(float2*)&g_pout[c][row1][nb * 8 + 2 * t] = make_float2(o[nb][2], o[nb][3]);
    }
    if (t == 0) {
        g_pm[c][row0] = m0; g_pl[c][row0] = l0;
        g_pm[c][row1] = m1; g_pl[c][row1] = l1;
    }
}

// Combine: one warp per row. Fully unrolled; inactive chunks are zero-filled
// (.bss, never written) so they contribute exactly 0 — branch-free, max MLP.
__global__ __launch_bounds__(256)
void attn_phase2(float* __restrict__ out) {
    const int row  = blockIdx.x * 8 + (threadIdx.x >> 5);
    const int lane = threadIdx.x & 31;

    float pm[MAXC], pl[MAXC];
    #pragma unroll
    for (int c = 0; c < MAXC; c++) { pm[c] = g_pm[c][row]; pl[c] = g_pl[c][row]; }

    float gmax = pm[0];
    #pragma unroll
    for (int c = 1; c < MAXC; c++) gmax = fmaxf(gmax, pm[c]);

    float denom = 0.f, o0 = 0.f, o1 = 0.f;
    #pragma unroll
    for (int c = 0; c < MAXC; c++) {
        float w = ex2f(pm[c] - gmax);
        denom = fmaf(w, pl[c], denom);
        o0 = fmaf(w, g_pout[c][row][lane],      o0);
        o1 = fmaf(w, g_pout[c][row][lane + 32], o1);
    }
    float inv = 1.0f / denom;
    out[(size_t)row * DKE + lane]      = o0 * inv;
    out[(size_t)row * DKE + lane + 32] = o1 * inv;
}

extern "C" void kernel_launch(void* const* d_in, const int* in_sizes, int n_in,
                              void* d_out, int out_size) {
    const float* q = (const float*)d_in[0];
    const float* k = (const float*)d_in[1];
    const float* v = (const float*)d_in[2];
    float* out = (float*)d_out;

    prep_kv<<<NTILE * 2, 256>>>(k, v);
    dim3 grid1(MAXC, NQT);
    attn_phase1<<<grid1, 256>>>(q);
    attn_phase2<<<SEQ / 8, 256>>>(out);
}